// round 4
// baseline (speedup 1.0000x reference)
#include <cuda_runtime.h>
#include <math.h>

#define NB 128
#define NR 4096
#define ND 256
#define TILES (NR / 8)   // 512 blocks per sample, 8 rows per block

// Scratch (device globals — no allocation allowed)
__device__ float g_sims[NB * NR];   // dot(r_i,q)/||r_i||  (missing /||q||)
__device__ int   g_idx [NB * NR];   // compacted masked indices per sample
__device__ int   g_cnt [NB];        // arrival counters (self-resetting)

// ---------------------------------------------------------------------------
// Single fused kernel: full-tensor copy + sims, then the LAST block per
// sample performs the masked-softmax finalize for that sample.
// grid = (TILES, NB), block = 256 (8 warps = 8 rows).
// ---------------------------------------------------------------------------
__global__ void __launch_bounds__(256, 8)
k_fused(const float4* __restrict__ reps4,
        float4* __restrict__ out4,
        const float* __restrict__ reps,
        float* __restrict__ out,
        const int* __restrict__ qrel,
        const float* __restrict__ thr_raw,
        const float* __restrict__ str_raw,
        const float* __restrict__ wscale,
        const float* __restrict__ temp_p) {
    int b    = blockIdx.y;
    int warp = threadIdx.x >> 5;
    int lane = threadIdx.x & 31;
    int row  = blockIdx.x * 8 + warp;
    int t    = threadIdx.x;

    int qidx = __ldg(&qrel[b]);
    qidx = max(0, min(NR - 1, qidx));

    // ---- phase 1: copy 8 rows + accumulate dot(r,q) and ||r||^2 ----
    const float4* q4 = reps4 + ((size_t)b * NR + (size_t)qidx) * (ND / 4);
    size_t base = ((size_t)b * NR + (size_t)row) * (ND / 4);

    float dot = 0.f, ss = 0.f;
    #pragma unroll
    for (int k = 0; k < 2; k++) {
        int idx = lane + 32 * k;
        float4 v  = reps4[base + idx];
        float4 qv = __ldg(&q4[idx]);          // L2-resident (1KB per sample)
        out4[base + idx] = v;                 // the mandatory output copy
        dot += v.x * qv.x + v.y * qv.y + v.z * qv.z + v.w * qv.w;
        ss  += v.x * v.x  + v.y * v.y  + v.z * v.z  + v.w * v.w;
    }
    #pragma unroll
    for (int o = 16; o > 0; o >>= 1) {
        dot += __shfl_down_sync(0xffffffffu, dot, o);
        ss  += __shfl_down_sync(0xffffffffu, ss,  o);
    }
    if (lane == 0) {
        float nrm = fmaxf(sqrtf(ss), 1e-12f);
        g_sims[(size_t)b * NR + row] = dot / nrm;
    }

    // ---- arrival protocol: last block per sample runs the finalize ----
    __threadfence();            // release: sims + out stores visible
    __shared__ int s_last;
    __shared__ int s_cnt;
    __shared__ float s_redA[8];
    __shared__ float s_redB[8];
    __shared__ float s_bc0, s_bc1;
    __syncthreads();
    if (t == 0) {
        int old = atomicAdd(&g_cnt[b], 1);
        s_last = (old == TILES - 1);
        s_cnt = 0;
    }
    __syncthreads();
    if (!s_last) return;
    // acquire side: the atomicAdd chain + fence above orders all other
    // blocks' g_sims/out stores before this point.

    // ---- phase 2: finalize for sample b (cold path, runs once/sample) ----
    float threshold = 1.f / (1.f + expf(-thr_raw[0]));
    float strength  = 0.2f / (1.f + expf(-str_raw[0]));
    float ws        = wscale[0];
    float temp      = fminf(fmaxf(temp_p[0], 0.1f), 10.f);

    size_t qoff = ((size_t)b * NR + (size_t)qidx) * ND;
    float qv = reps[qoff + t];

    // ||q|| block reduction
    float s2 = qv * qv;
    #pragma unroll
    for (int o = 16; o > 0; o >>= 1) s2 += __shfl_down_sync(0xffffffffu, s2, o);
    if ((t & 31) == 0) s_redA[t >> 5] = s2;
    __syncthreads();
    if (t == 0) {
        float x = 0.f;
        #pragma unroll
        for (int i = 0; i < 8; i++) x += s_redA[i];
        s_bc0 = 1.f / fmaxf(sqrtf(x), 1e-12f);
    }
    __syncthreads();
    float inv_nq = s_bc0;

    const float* simsg = g_sims + (size_t)b * NR;
    int*         idxg  = g_idx  + (size_t)b * NR;

    // mask scan + compaction (L2-hot)
    float lmax = -3e38f;
    for (int i = t; i < NR; i += 256) {
        float s = (i == qidx) ? -1.0f : simsg[i] * inv_nq;
        if (s > threshold) {
            int p = atomicAdd(&s_cnt, 1);
            idxg[p] = i;
            lmax = fmaxf(lmax, s);
        }
    }
    #pragma unroll
    for (int o = 16; o > 0; o >>= 1)
        lmax = fmaxf(lmax, __shfl_down_sync(0xffffffffu, lmax, o));
    if ((t & 31) == 0) s_redA[t >> 5] = lmax;
    __syncthreads();

    int cnt = s_cnt;
    if (cnt == 0) {
        // no valid neighbor: row stays q (matches has_valid=false branch)
        out[qoff + t] = qv;
        if (t == 0) g_cnt[b] = 0;   // reset for next graph replay
        return;
    }

    if (t == 0) {
        float x = s_redA[0];
        #pragma unroll
        for (int i = 1; i < 8; i++) x = fmaxf(x, s_redA[i]);
        s_bc0 = x;
    }
    __syncthreads();
    float m = s_bc0 / temp;   // max logit over masked entries

    // Z = softmax denom; S = sum of pre-normalized adjusted weights
    float lZ = 0.f, lS = 0.f;
    for (int j = t; j < cnt; j += 256) {
        float s  = simsg[idxg[j]] * inv_nq;
        float e  = expf(s / temp - m);
        float sw = 1.f / (1.f + expf(-(s - threshold) * 10.f));
        lZ += e;
        lS += e * sw * (1.f + ws * s);
    }
    #pragma unroll
    for (int o = 16; o > 0; o >>= 1) {
        lZ += __shfl_down_sync(0xffffffffu, lZ, o);
        lS += __shfl_down_sync(0xffffffffu, lS, o);
    }
    if ((t & 31) == 0) { s_redA[t >> 5] = lZ; s_redB[t >> 5] = lS; }
    __syncthreads();
    if (t == 0) {
        float z = 0.f, sS = 0.f;
        #pragma unroll
        for (int i = 0; i < 8; i++) { z += s_redA[i]; sS += s_redB[i]; }
        s_bc0 = z; s_bc1 = sS;
    }
    __syncthreads();
    float Z = s_bc0, S = s_bc1;
    // adjusted_i = (e_i*sw_i*(1+ws*s_i)/Z) / (S/Z + 1e-8)
    float scale = 1.f / (Z * (S / Z + 1e-8f));

    const float* rb = reps + (size_t)b * NR * ND;
    float acc = 0.f;
    for (int j = 0; j < cnt; j++) {
        int i = idxg[j];
        float s  = simsg[i] * inv_nq;
        float e  = expf(s / temp - m);
        float sw = 1.f / (1.f + expf(-(s - threshold) * 10.f));
        float a  = e * sw * (1.f + ws * s) * scale;
        acc += a * rb[(size_t)i * ND + t];
    }

    out[qoff + t] = (1.f - strength) * qv + strength * acc;
    if (t == 0) g_cnt[b] = 0;       // reset for next graph replay
}

// ---------------------------------------------------------------------------
extern "C" void kernel_launch(void* const* d_in, const int* in_sizes, int n_in,
                              void* d_out, int out_size) {
    const float* reps  = (const float*)d_in[0];
    const int*   qrel  = (const int*)d_in[1];
    const float* thr   = (const float*)d_in[2];
    const float* str   = (const float*)d_in[3];
    const float* wsc   = (const float*)d_in[4];
    const float* tmp   = (const float*)d_in[5];
    float*       out   = (float*)d_out;

    dim3 grid(TILES, NB);
    k_fused<<<grid, 256>>>(reinterpret_cast<const float4*>(reps),
                           reinterpret_cast<float4*>(out),
                           reps, out, qrel, thr, str, wsc, tmp);
}